// round 17
// baseline (speedup 1.0000x reference)
#include <cuda_runtime.h>
#include <cuda_fp16.h>

typedef unsigned long long u64;
typedef unsigned int u32;

#define HIDN 10
#define CCH  256
#define HWV  16384
#define NIMG 8
#define NPAIR 65536
#define NPIX 131072
// output offsets (floats)
#define OUT_XHL  1310720
#define OUT_ATTU 2621440
#define OUT_ATTL 2752512

// scratch: 22 planes of dots; float view [22][131072]
__device__ __align__(16) u64 g_hacc[22 * NPAIR];

// ---------- packed f32x2 helpers (k2) ----------
__device__ __forceinline__ u64 ffma2(u64 a, u64 b, u64 c) {
    u64 d; asm("fma.rn.f32x2 %0,%1,%2,%3;" : "=l"(d) : "l"(a), "l"(b), "l"(c)); return d;
}
__device__ __forceinline__ u64 fmul2(u64 a, u64 b) {
    u64 d; asm("mul.rn.f32x2 %0,%1,%2;" : "=l"(d) : "l"(a), "l"(b)); return d;
}
__device__ __forceinline__ u64 fadd2(u64 a, u64 b) {
    u64 d; asm("add.rn.f32x2 %0,%1,%2;" : "=l"(d) : "l"(a), "l"(b)); return d;
}
__device__ __forceinline__ u64 pack2(float x, float y) {
    u64 d; asm("mov.b64 %0,{%1,%2};" : "=l"(d) : "f"(x), "f"(y)); return d;
}
__device__ __forceinline__ void unpack2(u64 a, float& x, float& y) {
    asm("mov.b64 {%0,%1},%2;" : "=f"(x), "=f"(y) : "l"(a));
}
__device__ __forceinline__ u64 dup2(float x) { return pack2(x, x); }
__device__ __forceinline__ u64 relu2(u64 a) {
    float x, y; unpack2(a, x, y);
    return pack2(fmaxf(x, 0.f), fmaxf(y, 0.f));
}
__device__ __forceinline__ u64 sigmoid2(u64 a) {
    float x, y; unpack2(a, x, y);
    x = __fdividef(1.f, 1.f + __expf(-x));
    y = __fdividef(1.f, 1.f + __expf(-y));
    return pack2(x, y);
}
__device__ __forceinline__ u64 neg2(u64 a) { return a ^ 0x8000000080000000ULL; }

struct uu2 { u64 x, y; };
__device__ __forceinline__ uu2 lds2(const u64* p) {
    uu2 r;
    asm("ld.shared.v2.u64 {%0,%1}, [%2];" : "=l"(r.x), "=l"(r.y) : "l"(__cvta_generic_to_shared(p)));
    return r;
}

// ---------- fp16 mma helpers (k1) ----------
__device__ __forceinline__ u32 f16b(float f) {
    return (u32)__half_as_ushort(__float2half_rn(f));
}
__device__ __forceinline__ u32 cvt_f16x2(float hi, float lo) {
    u32 d; asm("cvt.rn.f16x2.f32 %0,%1,%2;" : "=r"(d) : "f"(hi), "f"(lo)); return d;
}
__device__ __forceinline__ void mma_f16(float (&d)[4], const u32 (&a)[4], const u32* b) {
    asm volatile(
        "mma.sync.aligned.m16n8k16.row.col.f32.f16.f16.f32 "
        "{%0,%1,%2,%3},{%4,%5,%6,%7},{%8,%9},{%0,%1,%2,%3};"
        : "+f"(d[0]), "+f"(d[1]), "+f"(d[2]), "+f"(d[3])
        : "r"(a[0]), "r"(a[1]), "r"(a[2]), "r"(a[3]), "r"(b[0]), "r"(b[1]));
}
__device__ __forceinline__ void cp16(float* dst, const float* src) {
    u32 ds = (u32)__cvta_generic_to_shared(dst);
    asm volatile("cp.async.cg.shared.global [%0], [%1], 16;" :: "r"(ds), "l"(src));
}
#define CP_COMMIT() asm volatile("cp.async.commit_group;" ::: "memory")
#define CP_WAIT2()  asm volatile("cp.async.wait_group 2;" ::: "memory")

// ============================================================================
// Kernel 1 (tensor): hacc[22][pix] = W[22x256] . hfea[256][pix]
// fp16 m16n8k16, fp32 accum. 128-px chunks (1024), persistent 296 blocks
// (2/SM), 4-stage cp.async ring, one __syncthreads per tile.
// ============================================================================

#define CHW    128                    // pixels per chunk
#define NCHUNK 1024
#define K1_GRID 296
#define HROW   132                    // 128 + 4 pad: conflict-free B-frag reads
#define HBUF   (32 * HROW)            // one 32-channel tile (floats)
#define K1_STAGES 4
#define K1_SMEM_BYTES ((4096 + K1_STAGES * HBUF) * 4)

__global__ void __launch_bounds__(256, 2) k1t_kernel(const float* __restrict__ hfea,
                                                     const float* __restrict__ w_pdp1,
                                                     const float* __restrict__ w_dua,
                                                     const float* __restrict__ w_dla) {
    extern __shared__ u32 smemu[];
    u32*   Wh   = smemu;              // [2 mtile][16 ks16][32 lane][4] = 4096 (fp16x2)
    float* hbuf = (float*)(smemu + 4096);  // K1_STAGES x HBUF floats

    const int tid = threadIdx.x;
    const int w   = tid >> 5;
    const int l   = tid & 31;
    const int bid = blockIdx.x;

    // ---- weight prep: fp16, pre-swizzled into m16n8k16 A-frag order ----
    for (int sidx = tid; sidx < 1024; sidx += 256) {
        int t = sidx >> 9, rem = sidx & 511, s = rem >> 5, ln = rem & 31;
#pragma unroll
        for (int r = 0; r < 4; r++) {
            int row = 16 * t + (ln >> 2) + 8 * (r & 1);
            int k0  = 16 * s + (ln & 3) * 2 + 8 * (r >> 1);
            float v0 = 0.f, v1 = 0.f;
            if (row < 20)       { v0 = w_pdp1[row * 276 + k0]; v1 = w_pdp1[row * 276 + k0 + 1]; }
            else if (row == 20) { v0 = w_dua[k0]; v1 = w_dua[k0 + 1]; }
            else if (row == 21) { v0 = w_dla[k0]; v1 = w_dla[k0 + 1]; }
            Wh[sidx * 4 + r] = (f16b(v1) << 16) | f16b(v0);
        }
    }

    const int total = 8 * ((NCHUNK - bid + K1_GRID - 1) / K1_GRID);  // tiles for this block

    // tile loader: 32 channels x 128 px; thread -> row tid>>3, 4 x 16B segs
    const int lrow = tid >> 3;
    const int seg0 = tid & 7;
    auto issue_load = [&](int g) {
        const int c2  = bid + K1_GRID * (g >> 3);
        const int n2  = c2 >> 7;
        const int hw2 = (c2 & 127) << 7;
        const int kk  = g & 7;
        const float* srcr = hfea + ((size_t)(n2 * CCH + kk * 32) + lrow) * HWV + hw2;
        float* dstr = hbuf + (g & 3) * HBUF + lrow * HROW;
#pragma unroll
        for (int j = 0; j < 4; j++) { int seg = seg0 + j * 8; cp16(dstr + seg * 4, srcr + seg * 4); }
    };

    issue_load(0); CP_COMMIT();
    issue_load(1); CP_COMMIT();
    issue_load(2); CP_COMMIT();
    __syncthreads();   // weights ready before first compute

    float Cf[2][2][4];
#pragma unroll
    for (int t = 0; t < 2; t++)
#pragma unroll
        for (int nt = 0; nt < 2; nt++)
#pragma unroll
            for (int r = 0; r < 4; r++) Cf[t][nt][r] = 0.f;

#pragma unroll 1
    for (int gi = 0; gi < total; gi++) {
        CP_WAIT2();
        __syncthreads();     // all warps done with stage (gi-1)&3; data of gi visible
        if (gi + 3 < total) issue_load(gi + 3);
        CP_COMMIT();

        const float* hb = hbuf + (gi & 3) * HBUF;
#pragma unroll
        for (int ks = 0; ks < 2; ks++) {
            const int s = (gi & 7) * 2 + ks;
            u32 ah[2][4];
#pragma unroll
            for (int t = 0; t < 2; t++) {
                uint4 h4 = *(const uint4*)(Wh + ((t * 16 + s) * 32 + l) * 4);
                ah[t][0] = h4.x; ah[t][1] = h4.y; ah[t][2] = h4.z; ah[t][3] = h4.w;
            }
            u32 bh[2][2];
            const int rb = (16 * ks + (l & 3) * 2) * HROW + (l >> 2);
#pragma unroll
            for (int nt = 0; nt < 2; nt++) {
                const int idx = rb + w * 16 + nt * 8;
                float f00 = hb[idx];
                float f01 = hb[idx + HROW];
                float f10 = hb[idx + 8 * HROW];
                float f11 = hb[idx + 9 * HROW];
                bh[nt][0] = cvt_f16x2(f01, f00);
                bh[nt][1] = cvt_f16x2(f11, f10);
            }
#pragma unroll
            for (int t = 0; t < 2; t++)
#pragma unroll
                for (int nt = 0; nt < 2; nt++)
                    mma_f16(Cf[t][nt], ah[t], bh[nt]);
        }

        if ((gi & 7) == 7) {
            // ---- store chunk: rows 0..21, float2 per lane ----
            const int c   = bid + K1_GRID * (gi >> 3);
            const int n   = c >> 7;
            const int hw0 = (c & 127) << 7;
            float* ob = (float*)g_hacc;
            const int lr  = l >> 2;
            const int pxo = 2 * (l & 3);
            const size_t pbase = (size_t)n * HWV + hw0;
#pragma unroll
            for (int t = 0; t < 2; t++)
#pragma unroll
                for (int nt = 0; nt < 2; nt++) {
                    const int px = w * 16 + nt * 8 + pxo;
                    const int row0 = 16 * t + lr;
                    if (row0 < 22) {
                        float2 v; v.x = Cf[t][nt][0]; v.y = Cf[t][nt][1];
                        *(float2*)(ob + (size_t)row0 * NPIX + pbase + px) = v;
                    }
                    const int row1 = 16 * t + lr + 8;
                    if (row1 < 22) {
                        float2 v; v.x = Cf[t][nt][2]; v.y = Cf[t][nt][3];
                        *(float2*)(ob + (size_t)row1 * NPIX + pbase + px) = v;
                    }
                }
#pragma unroll
            for (int t = 0; t < 2; t++)
#pragma unroll
                for (int nt = 0; nt < 2; nt++)
#pragma unroll
                    for (int r = 0; r < 4; r++) Cf[t][nt][r] = 0.f;
        }
    }
}

// ============================================================================
// Kernel 2: HID=10 graph ops, packed over the pixel pair (R12 version).
// ============================================================================

struct P27 {
    const float* a[27];
    float* out;
};

#define K2T 128

__global__ void __launch_bounds__(K2T, 4) k2_kernel(P27 p) {
    const float* g_xhu  = p.a[1];
    const float* g_xhl  = p.a[2];
    const float* g_xf   = p.a[3];
    const float* g_xp   = p.a[4];
    const float* w_pdp1 = p.a[5];
    const float* w_pdp2 = p.a[6];
    const float* w_att  = p.a[7];
    const float* b_att  = p.a[8];
    const float* w_cua  = p.a[9];
    const float* b_cua  = p.a[10];
    const float* w_cu   = p.a[11];
    const float* w_cla  = p.a[12];
    const float* b_cla  = p.a[13];
    const float* w_cl   = p.a[14];
    const float* w_dua  = p.a[15];
    const float* b_dua  = p.a[16];
    const float* w_du   = p.a[17];
    const float* w_dla  = p.a[18];
    const float* b_dla  = p.a[19];
    const float* w_dl   = p.a[20];
    const float* w_ugu  = p.a[21];
    const float* b_ugu  = p.a[22];
    const float* w_ucu  = p.a[23];
    const float* w_ugl  = p.a[24];
    const float* b_ugl  = p.a[25];
    const float* w_ucl  = p.a[26];
    float* out = p.out;

    __shared__ __align__(16) u64 s_small[2152];
    __shared__ u64 s_dpu[K2T * 11];

    const int tid = threadIdx.x;
    {
        for (int i = tid; i < 400; i += K2T) { int o = i / 20, k = i % 20; s_small[i] = dup2(w_pdp1[o * 276 + 256 + k]); }
        for (int i = tid; i < 200; i += K2T) s_small[400 + i] = dup2(w_pdp2[i]);
        for (int i = tid; i < 22;  i += K2T) s_small[600 + i] = (i < 20) ? dup2(w_att[i]) : dup2(b_att[i - 20]);
        for (int i = tid; i < 44;  i += K2T) s_small[622 + i] = (i < 40) ? dup2(w_cua[i]) : dup2(b_cua[i - 40]);
        for (int i = tid; i < 200; i += K2T) s_small[666 + i] = dup2(w_cu[i]);
        for (int i = tid; i < 22;  i += K2T) s_small[866 + i] = (i < 20) ? dup2(w_cla[i]) : dup2(b_cla[i - 20]);
        for (int i = tid; i < 200; i += K2T) s_small[888 + i] = dup2(w_cl[i]);
        for (int i = tid; i < 21;  i += K2T) s_small[1088 + i] = (i < 20) ? dup2(w_dua[256 + i]) : dup2(b_dua[0]);
        for (int i = tid; i < 100; i += K2T) s_small[1110 + i] = dup2(w_du[i]);
        for (int i = tid; i < 21;  i += K2T) s_small[1210 + i] = (i < 20) ? dup2(w_dla[256 + i]) : dup2(b_dla[0]);
        for (int i = tid; i < 100; i += K2T) s_small[1232 + i] = dup2(w_dl[i]);
        for (int i = tid; i < 210; i += K2T) s_small[1332 + i] = (i < 200) ? dup2(w_ugu[i]) : dup2(b_ugu[i - 200]);
        for (int i = tid; i < 200; i += K2T) s_small[1542 + i] = dup2(w_ucu[i]);
        for (int i = tid; i < 210; i += K2T) s_small[1742 + i] = (i < 200) ? dup2(w_ugl[i]) : dup2(b_ugl[i - 200]);
        for (int i = tid; i < 200; i += K2T) s_small[1952 + i] = dup2(w_ucl[i]);
    }
    __syncthreads();

    const int pair = blockIdx.x * K2T + tid;
    const int pix  = pair * 2;
    const int n    = pix >> 14;
    const int hw   = pix & (HWV - 1);
    const size_t vb = (size_t)n * HIDN * HWV + hw;
    const u64* hac = g_hacc + pair;

    u64 xu[10], xl[10];
#pragma unroll
    for (int i = 0; i < 10; i++) {
        xu[i] = *(const u64*)(g_xhu + vb + (size_t)i * HWV);
        xl[i] = *(const u64*)(g_xhl + vb + (size_t)i * HWV);
    }

    u64 dpl[10];
    {
        u64 tt[20];
#pragma unroll
        for (int o = 0; o < 20; o++) {
            u64 a = hac[(size_t)o * NPAIR];
            const u64* wr = s_small + o * 20;
#pragma unroll
            for (int k = 0; k < 10; k += 2) {
                uu2 w = lds2(wr + k);
                a = ffma2(xu[k], w.x, a);
                a = ffma2(xu[k + 1], w.y, a);
            }
#pragma unroll
            for (int k = 0; k < 10; k += 2) {
                uu2 w = lds2(wr + 10 + k);
                a = ffma2(xl[k], w.x, a);
                a = ffma2(xl[k + 1], w.y, a);
            }
            tt[o] = relu2(a);
        }
#pragma unroll
        for (int o = 0; o < 10; o++) {
            u64 a = 0ULL, b = 0ULL;
#pragma unroll
            for (int i = 0; i < 10; i += 2) {
                uu2 wa = lds2(s_small + 400 + o * 10 + i);
                uu2 wb = lds2(s_small + 500 + o * 10 + i);
                a = ffma2(tt[i],      wa.x, a);
                a = ffma2(tt[i + 1],  wa.y, a);
                b = ffma2(tt[10 + i], wb.x, b);
                b = ffma2(tt[11 + i], wb.y, b);
            }
            s_dpu[tid * 11 + o] = relu2(a);
            dpl[o] = relu2(b);
        }
    }
    u64 agu, agl;
    {
        u64 a = s_small[620], b = s_small[621];
#pragma unroll
        for (int i = 0; i < 10; i += 2) {
            uu2 wa = lds2(s_small + 600 + i);
            uu2 wb = lds2(s_small + 610 + i);
            a = ffma2(xu[i], wa.x, a);
            a = ffma2(xu[i + 1], wa.y, a);
            b = ffma2(xl[i], wb.x, b);
            b = ffma2(xl[i + 1], wb.y, b);
        }
        agu = sigmoid2(a);
        agl = sigmoid2(b);
    }

    u64 xfv[10];
#pragma unroll
    for (int i = 0; i < 10; i++) xfv[i] = *(const u64*)(g_xf + vb + (size_t)i * HWV);

    // ================= U half =================
    {
        u64 msg[10];
#pragma unroll
        for (int i = 0; i < 10; i++) msg[i] = 0ULL;
#pragma unroll
        for (int pp = 0; pp < 4; pp++) {
            u64 xv[10];
            const float* xpp = g_xp + ((size_t)(pp * NIMG + n) * HIDN) * HWV + hw;
#pragma unroll
            for (int i = 0; i < 10; i++) xv[i] = *(const u64*)(xpp + (size_t)i * HWV);
            u64 s = s_small[662 + pp];
#pragma unroll
            for (int i = 0; i < 10; i += 2) {
                uu2 w = lds2(s_small + 622 + pp * 10 + i);
                s = ffma2(xv[i], w.x, s);
                s = ffma2(xv[i + 1], w.y, s);
            }
            u64 ca = sigmoid2(s);
#pragma unroll
            for (int i = 0; i < 10; i++) msg[i] = ffma2(xv[i], ca, msg[i]);
        }
        u64 m[10];
#pragma unroll
        for (int o = 0; o < 10; o++) {
            u64 a = 0ULL;
            const u64* wr = s_small + 666 + o * 20;
#pragma unroll
            for (int i = 0; i < 10; i += 2) {
                uu2 wa = lds2(wr + i);
                uu2 wb = lds2(wr + 10 + i);
                a = ffma2(xu[i],  wa.x, a);
                a = ffma2(xu[i + 1], wa.y, a);
                a = ffma2(msg[i], wb.x, a);
                a = ffma2(msg[i + 1], wb.y, a);
            }
            m[o] = relu2(a);
            m[o] = ffma2(dpl[o], agl, m[o]);
            m[o] = ffma2(xu[o],  agu, m[o]);
        }
        u64 attu;
        {
            u64 s = fadd2(hac[(size_t)20 * NPAIR], s_small[1108]);
#pragma unroll
            for (int i = 0; i < 10; i += 2) {
                uu2 wa = lds2(s_small + 1088 + i);
                uu2 wb = lds2(s_small + 1098 + i);
                s = ffma2(xfv[i], wa.x, s);
                s = ffma2(xfv[i + 1], wa.y, s);
                s = ffma2(xu[i],  wb.x, s);
                s = ffma2(xu[i + 1], wb.y, s);
            }
            attu = sigmoid2(s);
        }
        *(u64*)(out + OUT_ATTU + (size_t)n * HWV + hw) = attu;
        {
            u64 xfa[10];
#pragma unroll
            for (int i = 0; i < 10; i++) xfa[i] = fmul2(xfv[i], attu);
#pragma unroll
            for (int o = 0; o < 10; o++) {
                u64 a = 0ULL;
#pragma unroll
                for (int i = 0; i < 10; i += 2) {
                    uu2 w = lds2(s_small + 1110 + o * 10 + i);
                    a = ffma2(xfa[i], w.x, a);
                    a = ffma2(xfa[i + 1], w.y, a);
                }
                m[o] = fadd2(m[o], relu2(a));
            }
        }
#pragma unroll
        for (int o = 0; o < 10; o++) {
            u64 g  = s_small[1532 + o];
            u64 cd = 0ULL;
            const u64* wg = s_small + 1332 + o * 20;
            const u64* wc = s_small + 1542 + o * 20;
#pragma unroll
            for (int i = 0; i < 10; i += 2) {
                uu2 a1 = lds2(wg + i);
                uu2 a2 = lds2(wc + i);
                g  = ffma2(xu[i], a1.x, g);
                g  = ffma2(xu[i + 1], a1.y, g);
                cd = ffma2(xu[i], a2.x, cd);
                cd = ffma2(xu[i + 1], a2.y, cd);
            }
#pragma unroll
            for (int i = 0; i < 10; i += 2) {
                uu2 a1 = lds2(wg + 10 + i);
                uu2 a2 = lds2(wc + 10 + i);
                g  = ffma2(m[i], a1.x, g);
                g  = ffma2(m[i + 1], a1.y, g);
                cd = ffma2(m[i], a2.x, cd);
                cd = ffma2(m[i + 1], a2.y, cd);
            }
            g  = sigmoid2(g);
            cd = relu2(cd);
            u64 res = ffma2(g, fadd2(cd, neg2(xu[o])), xu[o]);
            *(u64*)(out + (size_t)(n * HIDN + o) * HWV + hw) = res;
        }
    }

    // ================= L half =================
    {
        u64 xlv[10], xf2[10];
#pragma unroll
        for (int i = 0; i < 10; i++) {
            xlv[i] = *(const u64*)(g_xhl + vb + (size_t)i * HWV);
            xf2[i] = *(const u64*)(g_xf  + vb + (size_t)i * HWV);
        }
        u64 msg[10];
#pragma unroll
        for (int i = 0; i < 10; i++) msg[i] = 0ULL;
#pragma unroll
        for (int pp = 0; pp < 2; pp++) {
            u64 xv[10];
            const float* xpp = g_xp + ((size_t)((4 + pp) * NIMG + n) * HIDN) * HWV + hw;
#pragma unroll
            for (int i = 0; i < 10; i++) xv[i] = *(const u64*)(xpp + (size_t)i * HWV);
            u64 s = s_small[886 + pp];
#pragma unroll
            for (int i = 0; i < 10; i += 2) {
                uu2 w = lds2(s_small + 866 + pp * 10 + i);
                s = ffma2(xv[i], w.x, s);
                s = ffma2(xv[i + 1], w.y, s);
            }
            u64 ca = sigmoid2(s);
#pragma unroll
            for (int i = 0; i < 10; i++) msg[i] = ffma2(xv[i], ca, msg[i]);
        }
        u64 m[10];
#pragma unroll
        for (int o = 0; o < 10; o++) {
            u64 a = 0ULL;
            const u64* wr = s_small + 888 + o * 20;
#pragma unroll
            for (int i = 0; i < 10; i += 2) {
                uu2 wa = lds2(wr + i);
                uu2 wb = lds2(wr + 10 + i);
                a = ffma2(xlv[i], wa.x, a);
                a = ffma2(xlv[i + 1], wa.y, a);
                a = ffma2(msg[i], wb.x, a);
                a = ffma2(msg[i + 1], wb.y, a);
            }
            m[o] = relu2(a);
            m[o] = ffma2(s_dpu[tid * 11 + o], agu, m[o]);
            m[o] = ffma2(xlv[o], agl, m[o]);
        }
        u64 attl;
        {
            u64 s = fadd2(hac[(size_t)21 * NPAIR], s_small[1230]);
#pragma unroll
            for (int i = 0; i < 10; i += 2) {
                uu2 wa = lds2(s_small + 1210 + i);
                uu2 wb = lds2(s_small + 1220 + i);
                s = ffma2(xf2[i], wa.x, s);
                s = ffma2(xf2[i + 1], wa.y, s);
                s = ffma2(xlv[i], wb.x, s);
                s = ffma2(xlv[i + 1], wb.y, s);
            }
            attl = sigmoid2(s);
        }
        *(u64*)(out + OUT_ATTL + (size_t)n * HWV + hw) = attl;
        {
            u64 xfa[10];
#pragma unroll
            for (int i = 0; i < 10; i++) xfa[i] = fmul2(xf2[i], attl);
#pragma unroll
            for (int o = 0; o < 10; o++) {
                u64 a = 0ULL;
#pragma unroll
                for (int i = 0; i < 10; i += 2) {
                    uu2 w = lds2(s_small + 1232 + o * 10 + i);
                    a = ffma2(xfa[i], w.x, a);
                    a = ffma2(xfa[i + 1], w.y, a);
                }
                m[o] = fadd2(m[o], relu2(a));
            }
        }
#pragma unroll
        for (int o = 0; o < 10; o++) {
            u64 g  = s_small[1942 + o];
            u64 cd = 0ULL;
            const u64* wg = s_small + 1742 + o * 20;
            const u64* wc = s_small + 1952 + o * 20;
#pragma unroll
            for (int i = 0; i < 10; i += 2) {
                uu2 a1 = lds2(wg + i);
                uu2 a2 = lds2(wc + i);
                g  = ffma2(xlv[i], a1.x, g);
                g  = ffma2(xlv[i + 1], a1.y, g);
                cd = ffma2(xlv[i], a2.x, cd);
                cd = ffma2(xlv[i + 1], a2.y, cd);
            }
#pragma unroll
            for (int i = 0; i < 10; i += 2) {
                uu2 a1 = lds2(wg + 10 + i);
                uu2 a2 = lds2(wc + 10 + i);
                g  = ffma2(m[i], a1.x, g);
                g  = ffma2(m[i + 1], a1.y, g);
                cd = ffma2(m[i], a2.x, cd);
                cd = ffma2(m[i + 1], a2.y, cd);
            }
            g  = sigmoid2(g);
            cd = relu2(cd);
            u64 res = ffma2(g, fadd2(cd, neg2(xlv[o])), xlv[o]);
            *(u64*)(out + OUT_XHL + (size_t)(n * HIDN + o) * HWV + hw) = res;
        }
    }
}

extern "C" void kernel_launch(void* const* d_in, const int* in_sizes, int n_in,
                              void* d_out, int out_size) {
    cudaFuncSetAttribute(k1t_kernel, cudaFuncAttributeMaxDynamicSharedMemorySize,
                         K1_SMEM_BYTES);
    k1t_kernel<<<K1_GRID, 256, K1_SMEM_BYTES>>>((const float*)d_in[0], (const float*)d_in[5],
                                                (const float*)d_in[15], (const float*)d_in[18]);
    P27 p;
    for (int i = 0; i < 27; i++) p.a[i] = (const float*)d_in[i];
    p.out = (float*)d_out;
    k2_kernel<<<512, K2T>>>(p);
}